// round 1
// baseline (speedup 1.0000x reference)
#include <cuda_runtime.h>

// ---------------------------------------------------------------------------
// Pose2Mesh collapsed-linear implementation.
//
// out columns k (151 total):
//   k in [0,10)   : pred_shape  (width 10)
//   k in [10,13)  : pred_camera (width 3)
//   k in [13,59)  : pred_phi    (width 46)
//   k in [59,79)  : pred_leaf   (width 20)
//   k in [79,151) : pose, t=k-79, j=t/3, o=t%3 (before root subtraction)
// ---------------------------------------------------------------------------

#define D_DIM   2048
#define NC      57      // J*3
#define NK      151
#define NKPAD   160
#define KSPLIT  16
#define H_DIM   512

// scratch (allocation-free: __device__ globals)
__device__ float g_M1[24 * 9];
__device__ float g_M2[24 * 9];
__device__ float g_bp1[72];
__device__ float g_bp2[72];
__device__ float g_Wpart[KSPLIT * 58 * NKPAD];
__device__ float g_W[NC * NKPAD];
__device__ float g_b[NKPAD];

// NEB1[j]*3 and NEB2[j]*3 (base offsets into the 57-float joint vector)
__constant__ int c_NB1[24] = {51,33,36,51,39,42,51,45,48,54,45,48,54,54,54,54,15,18,21,24,27,30,27,30};
__constant__ int c_NB2[24] = {54,51,51,54,33,36,54,39,42,51,39,42, 0,15,18, 0,54,54,15,18,21,24,21,24};

__constant__ int c_k0[4] = {0, 40, 79, 115};
__constant__ int c_kn[4] = {40, 39, 36, 36};

// ---------------------------------------------------------------------------
// Kernel 1: per-joint 3x3 matrices M1 = L1_w@R1, M2 = L2_w@R2 and bias dots
// ---------------------------------------------------------------------------
__global__ void compute_M_kernel(const float* __restrict__ L1_w, const float* __restrict__ L1_b,
                                 const float* __restrict__ L2_w, const float* __restrict__ L2_b,
                                 const float* __restrict__ R1,   const float* __restrict__ R2)
{
    int j    = blockIdx.x;       // 0..23
    int lane = threadIdx.x & 31;
    int w    = threadIdx.x >> 5; // 0..3

    for (int t = w; t < 24; t += 4) {
        float sum = 0.f;
        if (t < 9) {
            int c = t / 3, o = t % 3;
            const float* ap = L1_w + (j * 3 + c) * H_DIM;
            const float* rp = R1 + j * H_DIM * 3 + o;
            for (int h = lane; h < H_DIM; h += 32) sum = fmaf(ap[h], rp[h * 3], sum);
        } else if (t < 18) {
            int tt = t - 9; int c = tt / 3, o = tt % 3;
            const float* ap = L2_w + (j * 3 + c) * H_DIM;
            const float* rp = R2 + j * H_DIM * 3 + o;
            for (int h = lane; h < H_DIM; h += 32) sum = fmaf(ap[h], rp[h * 3], sum);
        } else if (t < 21) {
            int o = t - 18;
            const float* ap = L1_b + j * H_DIM;
            const float* rp = R1 + j * H_DIM * 3 + o;
            for (int h = lane; h < H_DIM; h += 32) sum = fmaf(ap[h], rp[h * 3], sum);
        } else {
            int o = t - 21;
            const float* ap = L2_b + j * H_DIM;
            const float* rp = R2 + j * H_DIM * 3 + o;
            for (int h = lane; h < H_DIM; h += 32) sum = fmaf(ap[h], rp[h * 3], sum);
        }
        #pragma unroll
        for (int d = 16; d > 0; d >>= 1) sum += __shfl_xor_sync(0xffffffffu, sum, d);
        if (lane == 0) {
            if      (t < 9)  g_M1[j * 9 + t]          = sum;
            else if (t < 18) g_M2[j * 9 + (t - 9)]    = sum;
            else if (t < 21) g_bp1[j * 3 + (t - 18)]  = sum;
            else             g_bp2[j * 3 + (t - 21)]  = sum;
        }
    }
}

// ---------------------------------------------------------------------------
// Kernel 2: fold W_enc into all heads: C(58,151) = [W_enc; b_enc](58,2048) @ Bcat(2048,151)
// split-K into KSPLIT partials (deterministic, no atomics)
// ---------------------------------------------------------------------------
__device__ __forceinline__ float fetchB(int f, int col,
                                        const float* __restrict__ Wsh, const float* __restrict__ Wca,
                                        const float* __restrict__ Wph, const float* __restrict__ Wlf,
                                        const float* __restrict__ Rf)
{
    if (col < 10)  return Wsh[f * 10 + col];
    if (col < 13)  return Wca[f * 3  + (col - 10)];
    if (col < 59)  return Wph[f * 46 + (col - 13)];
    if (col < 79)  return Wlf[f * 20 + (col - 59)];
    int t = col - 79;
    int j = t / 3, o = t - j * 3;
    return Rf[(j * D_DIM + f) * 3 + o];
}

__global__ void fold_gemm_kernel(const float* __restrict__ W_enc, const float* __restrict__ b_enc,
                                 const float* __restrict__ W_shape, const float* __restrict__ W_cam,
                                 const float* __restrict__ W_phi,   const float* __restrict__ W_leaf,
                                 const float* __restrict__ Rf)
{
    __shared__ float As[64][33];
    __shared__ float Bs[32][33];

    int ct  = blockIdx.x;              // column tile (5 tiles of 32 -> 160)
    int ks  = blockIdx.y;              // k-split index
    int tid = threadIdx.x;             // 256 threads
    int tx  = tid & 31;                // column within tile
    int ty  = tid >> 5;                // 0..7

    float acc[8];
    #pragma unroll
    for (int i = 0; i < 8; i++) acc[i] = 0.f;

    int kbase0 = ks * (D_DIM / KSPLIT);       // 128 K per split
    for (int kb = 0; kb < D_DIM / KSPLIT; kb += 32) {
        int kbase = kbase0 + kb;
        // load A chunk (rows 0..56 = W_enc, row 57 = b_enc, rows 58..63 = 0)
        for (int idx = tid; idx < 64 * 32; idx += 256) {
            int r = idx >> 5, kk = idx & 31;
            float v = 0.f;
            if (r < NC)       v = W_enc[r * D_DIM + kbase + kk];
            else if (r == NC) v = b_enc[kbase + kk];
            As[r][kk] = v;
        }
        // load B chunk (gathered from head weights / Rf)
        for (int idx = tid; idx < 32 * 32; idx += 256) {
            int kk = idx >> 5, cl = idx & 31;
            int gcol = ct * 32 + cl;
            int f = kbase + kk;
            Bs[kk][cl] = (gcol < NK) ? fetchB(f, gcol, W_shape, W_cam, W_phi, W_leaf, Rf) : 0.f;
        }
        __syncthreads();
        #pragma unroll
        for (int kk = 0; kk < 32; kk++) {
            float bv = Bs[kk][tx];
            #pragma unroll
            for (int i = 0; i < 8; i++)
                acc[i] = fmaf(As[ty + 8 * i][kk], bv, acc[i]);
        }
        __syncthreads();
    }

    int gcol = ct * 32 + tx;
    #pragma unroll
    for (int i = 0; i < 8; i++) {
        int r = ty + 8 * i;
        if (r < 58) g_Wpart[(ks * 58 + r) * NKPAD + gcol] = acc[i];
    }
}

// ---------------------------------------------------------------------------
// Kernel 3: reduce split-K partials, add constant biases
// ---------------------------------------------------------------------------
__global__ void finalize_kernel(const float* __restrict__ b_shape, const float* __restrict__ b_cam,
                                const float* __restrict__ b_phi,   const float* __restrict__ b_leaf,
                                const float* __restrict__ init_shape, const float* __restrict__ init_cam,
                                const float* __restrict__ reg_b)
{
    int row = blockIdx.x;    // 0..57
    int col = threadIdx.x;   // 0..159
    float s = 0.f;
    #pragma unroll
    for (int p = 0; p < KSPLIT; p++) s += g_Wpart[(p * 58 + row) * NKPAD + col];

    if (row < NC) {
        g_W[row * NKPAD + col] = s;
        return;
    }
    float b = 0.f;
    if      (col < 10)  b = b_shape[col] + init_shape[col];
    else if (col < 13)  b = b_cam[col - 10] + init_cam[col - 10];
    else if (col < 59)  b = b_phi[col - 13];
    else if (col < 79)  b = b_leaf[col - 59];
    else if (col < NK) {
        int t = col - 79;
        b = reg_b[t] + g_bp1[t] + g_bp2[t];
    }
    g_b[col] = (col < NK) ? (s + b) : 0.f;
}

// ---------------------------------------------------------------------------
// Kernel 4: main — out(B,151) = x(B,57) @ g_W + g_b, plus neighbor 3x3 terms
// and root subtraction for pose columns. grid = (B/128, 4 k-slices), 128 thr.
// ---------------------------------------------------------------------------
__global__ void __launch_bounds__(128)
main_kernel(const float* __restrict__ joints, float* __restrict__ out, int B)
{
    __shared__ float4 Ws4[NC][10];      // 40 columns of the folded W, as float4
    __shared__ float  bias_s[40];
    __shared__ float  Xs[128 * 59];     // staged joint rows (pad 59: conflict-free)
    __shared__ float  W0s[NC * 3];      // pose root columns (79..81)
    __shared__ float  b0s[3];
    __shared__ float  M1s[216], M2s[216];

    const int sl   = blockIdx.y;
    const int k0   = c_k0[sl];
    const int kn   = c_kn[sl];
    const bool pose = (sl >= 2);
    const int tid  = threadIdx.x;
    const int rb   = blockIdx.x * 128;
    const int nrows = min(128, B - rb);

    // output section offsets
    const int CAM_OFF   = B * 72;
    const int PHI_OFF   = CAM_OFF + B * 3;
    const int LEAF_OFF  = PHI_OFF + B * 46;
    const int SHAPE_OFF = LEAF_OFF + B * 20;

    // stage X coalesced
    for (int idx = tid; idx < nrows * NC; idx += 128) {
        int r = idx / NC, c = idx - r * NC;
        Xs[r * 59 + c] = joints[rb * NC + idx];
    }
    // load W slice
    for (int idx = tid; idx < NC * 40; idx += 128) {
        int c = idx / 40, kk = idx - c * 40;
        ((float*)Ws4)[c * 40 + kk] = (kk < kn) ? g_W[c * NKPAD + k0 + kk] : 0.f;
    }
    if (tid < 40) bias_s[tid] = (tid < kn) ? g_b[k0 + tid] : 0.f;
    if (pose) {
        for (int idx = tid; idx < NC * 3; idx += 128) {
            int c = idx / 3, o = idx - c * 3;
            W0s[idx] = g_W[c * NKPAD + 79 + o];
        }
        if (tid < 3) b0s[tid] = g_b[79 + tid];
        for (int idx = tid; idx < 216; idx += 128) { M1s[idx] = g_M1[idx]; M2s[idx] = g_M2[idx]; }
    }
    __syncthreads();

    if (tid >= nrows) return;
    const int b = rb + tid;

    float x[NC];
    #pragma unroll
    for (int c = 0; c < NC; c++) x[c] = Xs[tid * 59 + c];

    float p0[3];
    if (pose) {
        #pragma unroll
        for (int o = 0; o < 3; o++) {
            float v = b0s[o];
            #pragma unroll
            for (int c = 0; c < NC; c++) v = fmaf(x[c], W0s[c * 3 + o], v);
            const int a1 = c_NB1[0], a2 = c_NB2[0];
            #pragma unroll
            for (int cc = 0; cc < 3; cc++) v = fmaf(x[a1 + cc], M1s[cc * 3 + o], v);
            #pragma unroll
            for (int cc = 0; cc < 3; cc++) v = fmaf(x[a2 + cc], M2s[cc * 3 + o], v);
            p0[o] = v;
        }
    }

    const int nch = (kn + 3) >> 2;
    for (int q = 0; q < nch; q++) {
        float4 acc = make_float4(bias_s[4 * q], bias_s[4 * q + 1],
                                 bias_s[4 * q + 2], bias_s[4 * q + 3]);
        #pragma unroll
        for (int c = 0; c < NC; c++) {
            float4 w = Ws4[c][q];
            float xc = x[c];
            acc.x = fmaf(xc, w.x, acc.x);
            acc.y = fmaf(xc, w.y, acc.y);
            acc.z = fmaf(xc, w.z, acc.z);
            acc.w = fmaf(xc, w.w, acc.w);
        }
        float comp[4] = {acc.x, acc.y, acc.z, acc.w};
        #pragma unroll
        for (int e = 0; e < 4; e++) {
            int kl = 4 * q + e;
            if (kl < kn) {
                int k = k0 + kl;
                float v = comp[e];
                if (!pose) {
                    if      (k < 10) out[SHAPE_OFF + b * 10 + k]        = v;
                    else if (k < 13) out[CAM_OFF   + b * 3  + (k - 10)] = v;
                    else if (k < 59) out[PHI_OFF   + b * 46 + (k - 13)] = v;
                    else             out[LEAF_OFF  + b * 20 + (k - 59)] = v;
                } else {
                    int t = k - 79;
                    int j = t / 3, o = t - j * 3;
                    const int a1 = c_NB1[j], a2 = c_NB2[j];
                    #pragma unroll
                    for (int cc = 0; cc < 3; cc++) v = fmaf(x[a1 + cc], M1s[j * 9 + cc * 3 + o], v);
                    #pragma unroll
                    for (int cc = 0; cc < 3; cc++) v = fmaf(x[a2 + cc], M2s[j * 9 + cc * 3 + o], v);
                    out[b * 72 + t] = v - p0[o];
                }
            }
        }
    }
}

// ---------------------------------------------------------------------------
extern "C" void kernel_launch(void* const* d_in, const int* in_sizes, int n_in,
                              void* d_out, int out_size)
{
    const float* joints     = (const float*)d_in[0];
    const float* W_enc      = (const float*)d_in[1];
    const float* b_enc      = (const float*)d_in[2];
    const float* W_shape    = (const float*)d_in[3];
    const float* b_shape    = (const float*)d_in[4];
    const float* W_cam      = (const float*)d_in[5];
    const float* b_cam      = (const float*)d_in[6];
    const float* W_phi      = (const float*)d_in[7];
    const float* b_phi      = (const float*)d_in[8];
    const float* W_leaf     = (const float*)d_in[9];
    const float* b_leaf     = (const float*)d_in[10];
    const float* init_shape = (const float*)d_in[11];
    const float* init_cam   = (const float*)d_in[12];
    const float* L1_w       = (const float*)d_in[13];
    const float* L1_b       = (const float*)d_in[14];
    const float* L2_w       = (const float*)d_in[15];
    const float* L2_b       = (const float*)d_in[16];
    const float* Rf         = (const float*)d_in[17];
    const float* R1         = (const float*)d_in[18];
    const float* R2         = (const float*)d_in[19];
    const float* reg_b      = (const float*)d_in[20];

    int B = in_sizes[0] / NC;

    compute_M_kernel<<<24, 128>>>(L1_w, L1_b, L2_w, L2_b, R1, R2);
    fold_gemm_kernel<<<dim3(5, KSPLIT), 256>>>(W_enc, b_enc, W_shape, W_cam, W_phi, W_leaf, Rf);
    finalize_kernel<<<58, NKPAD>>>(b_shape, b_cam, b_phi, b_leaf, init_shape, init_cam, reg_b);
    main_kernel<<<dim3((B + 127) / 128, 4), 128>>>(joints, (float*)d_out, B);
}

// round 2
// speedup vs baseline: 1.5299x; 1.5299x over previous
#include <cuda_runtime.h>

// ---------------------------------------------------------------------------
// Pose2Mesh fully-collapsed linear implementation.
// Everything (heads, neighbor 3x3 contractions, root subtraction) is folded
// into a single dense W'(57 x 151) + b'(151); the main kernel is a pure
// small GEMM: out(B,151) = x(B,57) @ W' + b'.
//
// out columns k (151 total):
//   k in [0,10)   : pred_shape
//   k in [10,13)  : pred_camera
//   k in [13,59)  : pred_phi
//   k in [59,79)  : pred_leaf
//   k in [79,151) : pred_pose (root-subtracted), t=k-79, j=t/3, o=t%3
// ---------------------------------------------------------------------------

#define D_DIM   2048
#define NC      57      // J*3
#define NK      151
#define NKPAD   160
#define KSPLIT  32
#define H_DIM   512
#define SLICE_W 12
#define NSLICES 13      // ceil(151/12)
#define ROWS_PB 128

// scratch (allocation-free: __device__ globals)
__device__ float g_M1[24 * 9];
__device__ float g_M2[24 * 9];
__device__ float g_bp1[72];
__device__ float g_bp2[72];
__device__ float g_Wpart[KSPLIT * 58 * NKPAD];
__device__ float g_W[NC * NKPAD];
__device__ float g_b[NKPAD];

// NEB1[j]*3 and NEB2[j]*3 (base offsets into the 57-float joint vector)
__constant__ int c_NB1[24] = {51,33,36,51,39,42,51,45,48,54,45,48,54,54,54,54,15,18,21,24,27,30,27,30};
__constant__ int c_NB2[24] = {54,51,51,54,33,36,54,39,42,51,39,42, 0,15,18, 0,54,54,15,18,21,24,21,24};

// ---------------------------------------------------------------------------
// Kernel 1: per-joint 3x3 matrices M1 = L1_w@R1, M2 = L2_w@R2 and bias dots
// grid (24, 6) x 128 threads: one warp per (j, t) reduction.
// ---------------------------------------------------------------------------
__global__ void compute_M_kernel(const float* __restrict__ L1_w, const float* __restrict__ L1_b,
                                 const float* __restrict__ L2_w, const float* __restrict__ L2_b,
                                 const float* __restrict__ R1,   const float* __restrict__ R2)
{
    int j    = blockIdx.x;                           // 0..23
    int lane = threadIdx.x & 31;
    int t    = blockIdx.y * 4 + (threadIdx.x >> 5);  // 0..23

    float sum = 0.f;
    if (t < 9) {
        int c = t / 3, o = t % 3;
        const float* ap = L1_w + (j * 3 + c) * H_DIM;
        const float* rp = R1 + j * H_DIM * 3 + o;
        for (int h = lane; h < H_DIM; h += 32) sum = fmaf(ap[h], rp[h * 3], sum);
    } else if (t < 18) {
        int tt = t - 9; int c = tt / 3, o = tt % 3;
        const float* ap = L2_w + (j * 3 + c) * H_DIM;
        const float* rp = R2 + j * H_DIM * 3 + o;
        for (int h = lane; h < H_DIM; h += 32) sum = fmaf(ap[h], rp[h * 3], sum);
    } else if (t < 21) {
        int o = t - 18;
        const float* ap = L1_b + j * H_DIM;
        const float* rp = R1 + j * H_DIM * 3 + o;
        for (int h = lane; h < H_DIM; h += 32) sum = fmaf(ap[h], rp[h * 3], sum);
    } else {
        int o = t - 21;
        const float* ap = L2_b + j * H_DIM;
        const float* rp = R2 + j * H_DIM * 3 + o;
        for (int h = lane; h < H_DIM; h += 32) sum = fmaf(ap[h], rp[h * 3], sum);
    }
    #pragma unroll
    for (int d = 16; d > 0; d >>= 1) sum += __shfl_xor_sync(0xffffffffu, sum, d);
    if (lane == 0) {
        if      (t < 9)  g_M1[j * 9 + t]          = sum;
        else if (t < 18) g_M2[j * 9 + (t - 9)]    = sum;
        else if (t < 21) g_bp1[j * 3 + (t - 18)]  = sum;
        else             g_bp2[j * 3 + (t - 21)]  = sum;
    }
}

// ---------------------------------------------------------------------------
// Kernel 2: fold W_enc into all heads: C(58,151) = [W_enc; b_enc] @ Bcat
// split-K into KSPLIT partials (deterministic, no atomics)
// ---------------------------------------------------------------------------
__device__ __forceinline__ float fetchB(int f, int col,
                                        const float* __restrict__ Wsh, const float* __restrict__ Wca,
                                        const float* __restrict__ Wph, const float* __restrict__ Wlf,
                                        const float* __restrict__ Rf)
{
    if (col < 10)  return Wsh[f * 10 + col];
    if (col < 13)  return Wca[f * 3  + (col - 10)];
    if (col < 59)  return Wph[f * 46 + (col - 13)];
    if (col < 79)  return Wlf[f * 20 + (col - 59)];
    int t = col - 79;
    int j = t / 3, o = t - j * 3;
    return Rf[(j * D_DIM + f) * 3 + o];
}

__global__ void fold_gemm_kernel(const float* __restrict__ W_enc, const float* __restrict__ b_enc,
                                 const float* __restrict__ W_shape, const float* __restrict__ W_cam,
                                 const float* __restrict__ W_phi,   const float* __restrict__ W_leaf,
                                 const float* __restrict__ Rf)
{
    __shared__ float As[64][33];
    __shared__ float Bs[32][33];

    int ct  = blockIdx.x;              // column tile (5 tiles of 32 -> 160)
    int ks  = blockIdx.y;              // k-split index (0..31)
    int tid = threadIdx.x;             // 256 threads
    int tx  = tid & 31;                // column within tile
    int ty  = tid >> 5;                // 0..7

    float acc[8];
    #pragma unroll
    for (int i = 0; i < 8; i++) acc[i] = 0.f;

    int kbase0 = ks * (D_DIM / KSPLIT);       // 64 K per split
    #pragma unroll
    for (int kb = 0; kb < D_DIM / KSPLIT; kb += 32) {
        int kbase = kbase0 + kb;
        for (int idx = tid; idx < 64 * 32; idx += 256) {
            int r = idx >> 5, kk = idx & 31;
            float v = 0.f;
            if (r < NC)       v = W_enc[r * D_DIM + kbase + kk];
            else if (r == NC) v = b_enc[kbase + kk];
            As[r][kk] = v;
        }
        for (int idx = tid; idx < 32 * 32; idx += 256) {
            int kk = idx >> 5, cl = idx & 31;
            int gcol = ct * 32 + cl;
            int f = kbase + kk;
            Bs[kk][cl] = (gcol < NK) ? fetchB(f, gcol, W_shape, W_cam, W_phi, W_leaf, Rf) : 0.f;
        }
        __syncthreads();
        #pragma unroll
        for (int kk = 0; kk < 32; kk++) {
            float bv = Bs[kk][tx];
            #pragma unroll
            for (int i = 0; i < 8; i++)
                acc[i] = fmaf(As[ty + 8 * i][kk], bv, acc[i]);
        }
        __syncthreads();
    }

    int gcol = ct * 32 + tx;
    #pragma unroll
    for (int i = 0; i < 8; i++) {
        int r = ty + 8 * i;
        if (r < 58) g_Wpart[(ks * 58 + r) * NKPAD + gcol] = acc[i];
    }
}

// ---------------------------------------------------------------------------
// Kernel 3: reduce split-K partials, fold neighbor 3x3 terms AND the root
// (joint 0) subtraction directly into W' and b'. Pads cols [151,160) to 0.
// ---------------------------------------------------------------------------
__global__ void finalize_kernel(const float* __restrict__ b_shape, const float* __restrict__ b_cam,
                                const float* __restrict__ b_phi,   const float* __restrict__ b_leaf,
                                const float* __restrict__ init_shape, const float* __restrict__ init_cam,
                                const float* __restrict__ reg_b)
{
    int row = blockIdx.x;    // 0..57
    int col = threadIdx.x;   // 0..159
    float s = 0.f;
    #pragma unroll
    for (int p = 0; p < KSPLIT; p++) s += g_Wpart[(p * 58 + row) * NKPAD + col];

    bool isPose = (col >= 79 && col < NK);
    int t = 0, j = 0, o = 0;
    float s0 = 0.f;
    if (isPose) {
        t = col - 79; j = t / 3; o = t - 3 * j;
        #pragma unroll
        for (int p = 0; p < KSPLIT; p++) s0 += g_Wpart[(p * 58 + row) * NKPAD + 79 + o];
    }

    if (row < NC) {
        float w;
        if (col >= NK) {
            w = 0.f;
        } else if (!isPose) {
            w = s;
        } else {
            w = s - s0;
            int a1 = c_NB1[j], a2 = c_NB2[j];
            if (row >= a1 && row < a1 + 3) w += g_M1[j * 9 + (row - a1) * 3 + o];
            if (row >= a2 && row < a2 + 3) w += g_M2[j * 9 + (row - a2) * 3 + o];
            // subtract joint-0 neighbor scatter (NB1[0]=51, NB2[0]=54)
            if (row >= 51 && row < 54) w -= g_M1[(row - 51) * 3 + o];
            if (row >= 54 && row < 57) w -= g_M2[(row - 54) * 3 + o];
        }
        g_W[row * NKPAD + col] = w;
    } else {
        float bv;
        if      (col >= NK) bv = 0.f;
        else if (col < 10)  bv = s + b_shape[col] + init_shape[col];
        else if (col < 13)  bv = s + b_cam[col - 10] + init_cam[col - 10];
        else if (col < 59)  bv = s + b_phi[col - 13];
        else if (col < 79)  bv = s + b_leaf[col - 59];
        else {
            float bt = s  + reg_b[t] + g_bp1[t] + g_bp2[t];
            float b0 = s0 + reg_b[o] + g_bp1[o] + g_bp2[o];
            bv = bt - b0;
        }
        g_b[col] = bv;
    }
}

// ---------------------------------------------------------------------------
// Kernel 4: main — out(B,151) = x(B,57) @ W' + b'. Pure branchless GEMM.
// grid = (B/128, 13 column-slices of 12), 128 threads, x read from smem
// (low regs -> high occupancy), W broadcast via LDS.128.
// ---------------------------------------------------------------------------
__global__ void __launch_bounds__(128)
main_kernel(const float* __restrict__ joints, float* __restrict__ out, int B)
{
    __shared__ float  Xs[ROWS_PB * NC];   // row-major, stride 57 (odd -> conflict-free)
    __shared__ float4 Ws4[NC][3];         // 12 columns of W' per block
    __shared__ float  bias_s[SLICE_W];

    const int tid = threadIdx.x;
    const int rb  = blockIdx.x * ROWS_PB;
    const int k0  = blockIdx.y * SLICE_W;          // 0,12,...,144 (all < 160)
    const int nrows = min(ROWS_PB, B - rb);

    // output section offsets (pose first, per metadata layout)
    const int CAM_OFF   = B * 72;
    const int PHI_OFF   = CAM_OFF + B * 3;
    const int LEAF_OFF  = PHI_OFF + B * 46;
    const int SHAPE_OFF = LEAF_OFF + B * 20;

    // stage X: perfectly coalesced gmem read, sequential smem write
    for (int idx = tid; idx < nrows * NC; idx += 128)
        Xs[idx] = joints[rb * NC + idx];

    // load this block's 12 W' columns
    for (int idx = tid; idx < NC * SLICE_W; idx += 128) {
        int c = idx / SLICE_W, e = idx - c * SLICE_W;
        ((float*)Ws4)[c * SLICE_W + e] = g_W[c * NKPAD + k0 + e];
    }
    if (tid < SLICE_W) bias_s[tid] = g_b[k0 + tid];
    __syncthreads();

    if (tid >= nrows) return;
    const int b = rb + tid;

    float4 a0 = make_float4(bias_s[0], bias_s[1], bias_s[2],  bias_s[3]);
    float4 a1 = make_float4(bias_s[4], bias_s[5], bias_s[6],  bias_s[7]);
    float4 a2 = make_float4(bias_s[8], bias_s[9], bias_s[10], bias_s[11]);

    const float* xrow = &Xs[tid * NC];
    #pragma unroll
    for (int c = 0; c < NC; c++) {
        float xc = xrow[c];
        float4 w0 = Ws4[c][0];
        float4 w1 = Ws4[c][1];
        float4 w2 = Ws4[c][2];
        a0.x = fmaf(xc, w0.x, a0.x); a0.y = fmaf(xc, w0.y, a0.y);
        a0.z = fmaf(xc, w0.z, a0.z); a0.w = fmaf(xc, w0.w, a0.w);
        a1.x = fmaf(xc, w1.x, a1.x); a1.y = fmaf(xc, w1.y, a1.y);
        a1.z = fmaf(xc, w1.z, a1.z); a1.w = fmaf(xc, w1.w, a1.w);
        a2.x = fmaf(xc, w2.x, a2.x); a2.y = fmaf(xc, w2.y, a2.y);
        a2.z = fmaf(xc, w2.z, a2.z); a2.w = fmaf(xc, w2.w, a2.w);
    }

    float v[SLICE_W] = {a0.x, a0.y, a0.z, a0.w, a1.x, a1.y, a1.z, a1.w,
                        a2.x, a2.y, a2.z, a2.w};
    #pragma unroll
    for (int e = 0; e < SLICE_W; e++) {
        int k = k0 + e;
        if (k < NK) {
            float val = v[e];
            if      (k < 10) out[SHAPE_OFF + b * 10 + k]        = val;
            else if (k < 13) out[CAM_OFF   + b * 3  + (k - 10)] = val;
            else if (k < 59) out[PHI_OFF   + b * 46 + (k - 13)] = val;
            else if (k < 79) out[LEAF_OFF  + b * 20 + (k - 59)] = val;
            else             out[b * 72 + (k - 79)]             = val;
        }
    }
}

// ---------------------------------------------------------------------------
extern "C" void kernel_launch(void* const* d_in, const int* in_sizes, int n_in,
                              void* d_out, int out_size)
{
    const float* joints     = (const float*)d_in[0];
    const float* W_enc      = (const float*)d_in[1];
    const float* b_enc      = (const float*)d_in[2];
    const float* W_shape    = (const float*)d_in[3];
    const float* b_shape    = (const float*)d_in[4];
    const float* W_cam      = (const float*)d_in[5];
    const float* b_cam      = (const float*)d_in[6];
    const float* W_phi      = (const float*)d_in[7];
    const float* b_phi      = (const float*)d_in[8];
    const float* W_leaf     = (const float*)d_in[9];
    const float* b_leaf     = (const float*)d_in[10];
    const float* init_shape = (const float*)d_in[11];
    const float* init_cam   = (const float*)d_in[12];
    const float* L1_w       = (const float*)d_in[13];
    const float* L1_b       = (const float*)d_in[14];
    const float* L2_w       = (const float*)d_in[15];
    const float* L2_b       = (const float*)d_in[16];
    const float* Rf         = (const float*)d_in[17];
    const float* R1         = (const float*)d_in[18];
    const float* R2         = (const float*)d_in[19];
    const float* reg_b      = (const float*)d_in[20];

    int B = in_sizes[0] / NC;

    compute_M_kernel<<<dim3(24, 6), 128>>>(L1_w, L1_b, L2_w, L2_b, R1, R2);
    fold_gemm_kernel<<<dim3(5, KSPLIT), 256>>>(W_enc, b_enc, W_shape, W_cam, W_phi, W_leaf, Rf);
    finalize_kernel<<<58, NKPAD>>>(b_shape, b_cam, b_phi, b_leaf, init_shape, init_cam, reg_b);
    main_kernel<<<dim3((B + ROWS_PB - 1) / ROWS_PB, NSLICES), 128>>>(joints, (float*)d_out, B);
}

// round 3
// speedup vs baseline: 1.8379x; 1.2013x over previous
#include <cuda_runtime.h>

// ---------------------------------------------------------------------------
// Pose2Mesh fully-collapsed linear implementation.
// All heads + neighbor 3x3 contractions + root subtraction folded into one
// dense W'(57 x 151) + b'(151); main kernel = out(B,151) = x(B,57) @ W' + b'.
// ---------------------------------------------------------------------------

#define D_DIM   2048
#define NC      57      // J*3
#define NK      151
#define NKPAD   160
#define KSPLIT  32
#define H_DIM   512
#define SLICE_W 16
#define NSLICES 10      // 160/16
#define RPB     64      // rows per block (main kernel)

// scratch (allocation-free: __device__ globals)
__device__ float g_M1[24 * 9];
__device__ float g_M2[24 * 9];
__device__ float g_bp1[72];
__device__ float g_bp2[72];
__device__ float g_Wpart[KSPLIT * 58 * NKPAD];
__device__ float g_W[NC * NKPAD];
__device__ float g_b[NKPAD];

// NEB1[j]*3 and NEB2[j]*3 (base offsets into the 57-float joint vector)
__constant__ int c_NB1[24] = {51,33,36,51,39,42,51,45,48,54,45,48,54,54,54,54,15,18,21,24,27,30,27,30};
__constant__ int c_NB2[24] = {54,51,51,54,33,36,54,39,42,51,39,42, 0,15,18, 0,54,54,15,18,21,24,21,24};

// ---------------------------------------------------------------------------
// Kernel A (fused): blocks [0,160) = fold GEMM split-K partials,
//                   blocks [160,232) = per-joint 3x3 matrices M1/M2 + bias dots
// 256 threads per block.
// ---------------------------------------------------------------------------
__device__ __forceinline__ float fetchB(int f, int col,
                                        const float* __restrict__ Wsh, const float* __restrict__ Wca,
                                        const float* __restrict__ Wph, const float* __restrict__ Wlf,
                                        const float* __restrict__ Rf)
{
    if (col < 10)  return Wsh[f * 10 + col];
    if (col < 13)  return Wca[f * 3  + (col - 10)];
    if (col < 59)  return Wph[f * 46 + (col - 13)];
    if (col < 79)  return Wlf[f * 20 + (col - 59)];
    int t = col - 79;
    int j = t / 3, o = t - j * 3;
    return Rf[(j * D_DIM + f) * 3 + o];
}

__global__ void __launch_bounds__(256)
precompute_kernel(const float* __restrict__ W_enc, const float* __restrict__ b_enc,
                  const float* __restrict__ W_shape, const float* __restrict__ W_cam,
                  const float* __restrict__ W_phi,   const float* __restrict__ W_leaf,
                  const float* __restrict__ Rf,
                  const float* __restrict__ L1_w, const float* __restrict__ L1_b,
                  const float* __restrict__ L2_w, const float* __restrict__ L2_b,
                  const float* __restrict__ R1,   const float* __restrict__ R2)
{
    int bx  = blockIdx.x;
    int tid = threadIdx.x;

    if (bx >= 5 * KSPLIT) {
        // ---- compute_M part: 72 blocks, warp w of group g handles task t=g*8+w
        int mb   = bx - 5 * KSPLIT;       // 0..71
        int j    = mb % 24;
        int g    = mb / 24;               // 0..2
        int lane = tid & 31;
        int t    = g * 8 + (tid >> 5);    // 0..23

        float sum = 0.f;
        if (t < 9) {
            int c = t / 3, o = t % 3;
            const float* ap = L1_w + (j * 3 + c) * H_DIM;
            const float* rp = R1 + j * H_DIM * 3 + o;
            for (int h = lane; h < H_DIM; h += 32) sum = fmaf(ap[h], rp[h * 3], sum);
        } else if (t < 18) {
            int tt = t - 9; int c = tt / 3, o = tt % 3;
            const float* ap = L2_w + (j * 3 + c) * H_DIM;
            const float* rp = R2 + j * H_DIM * 3 + o;
            for (int h = lane; h < H_DIM; h += 32) sum = fmaf(ap[h], rp[h * 3], sum);
        } else if (t < 21) {
            int o = t - 18;
            const float* ap = L1_b + j * H_DIM;
            const float* rp = R1 + j * H_DIM * 3 + o;
            for (int h = lane; h < H_DIM; h += 32) sum = fmaf(ap[h], rp[h * 3], sum);
        } else {
            int o = t - 21;
            const float* ap = L2_b + j * H_DIM;
            const float* rp = R2 + j * H_DIM * 3 + o;
            for (int h = lane; h < H_DIM; h += 32) sum = fmaf(ap[h], rp[h * 3], sum);
        }
        #pragma unroll
        for (int d = 16; d > 0; d >>= 1) sum += __shfl_xor_sync(0xffffffffu, sum, d);
        if (lane == 0) {
            if      (t < 9)  g_M1[j * 9 + t]          = sum;
            else if (t < 18) g_M2[j * 9 + (t - 9)]    = sum;
            else if (t < 21) g_bp1[j * 3 + (t - 18)]  = sum;
            else             g_bp2[j * 3 + (t - 21)]  = sum;
        }
        return;
    }

    // ---- fold GEMM part: C(58,151) = [W_enc; b_enc] @ Bcat, split-K partials
    __shared__ float As[64][33];
    __shared__ float Bs[32][33];

    int ct = bx % 5;              // column tile (5 tiles of 32 -> 160)
    int ks = bx / 5;              // k-split index (0..31)
    int tx = tid & 31;            // column within tile
    int ty = tid >> 5;            // 0..7

    float acc[8];
    #pragma unroll
    for (int i = 0; i < 8; i++) acc[i] = 0.f;

    int kbase0 = ks * (D_DIM / KSPLIT);       // 64 K per split
    #pragma unroll
    for (int kb = 0; kb < D_DIM / KSPLIT; kb += 32) {
        int kbase = kbase0 + kb;
        for (int idx = tid; idx < 64 * 32; idx += 256) {
            int r = idx >> 5, kk = idx & 31;
            float v = 0.f;
            if (r < NC)       v = W_enc[r * D_DIM + kbase + kk];
            else if (r == NC) v = b_enc[kbase + kk];
            As[r][kk] = v;
        }
        for (int idx = tid; idx < 32 * 32; idx += 256) {
            int kk = idx >> 5, cl = idx & 31;
            int gcol = ct * 32 + cl;
            int f = kbase + kk;
            Bs[kk][cl] = (gcol < NK) ? fetchB(f, gcol, W_shape, W_cam, W_phi, W_leaf, Rf) : 0.f;
        }
        __syncthreads();
        #pragma unroll
        for (int kk = 0; kk < 32; kk++) {
            float bv = Bs[kk][tx];
            #pragma unroll
            for (int i = 0; i < 8; i++)
                acc[i] = fmaf(As[ty + 8 * i][kk], bv, acc[i]);
        }
        __syncthreads();
    }

    int gcol = ct * 32 + tx;
    #pragma unroll
    for (int i = 0; i < 8; i++) {
        int r = ty + 8 * i;
        if (r < 58) g_Wpart[(ks * 58 + r) * NKPAD + gcol] = acc[i];
    }
}

// ---------------------------------------------------------------------------
// Kernel B: reduce split-K partials, fold neighbor 3x3 terms AND the root
// (joint 0) subtraction directly into W' and b'. Pads cols [151,160) to 0.
// ---------------------------------------------------------------------------
__global__ void finalize_kernel(const float* __restrict__ b_shape, const float* __restrict__ b_cam,
                                const float* __restrict__ b_phi,   const float* __restrict__ b_leaf,
                                const float* __restrict__ init_shape, const float* __restrict__ init_cam,
                                const float* __restrict__ reg_b)
{
    int row = blockIdx.x;    // 0..57
    int col = threadIdx.x;   // 0..159
    float s = 0.f;
    #pragma unroll
    for (int p = 0; p < KSPLIT; p++) s += g_Wpart[(p * 58 + row) * NKPAD + col];

    bool isPose = (col >= 79 && col < NK);
    int t = 0, j = 0, o = 0;
    float s0 = 0.f;
    if (isPose) {
        t = col - 79; j = t / 3; o = t - 3 * j;
        #pragma unroll
        for (int p = 0; p < KSPLIT; p++) s0 += g_Wpart[(p * 58 + row) * NKPAD + 79 + o];
    }

    if (row < NC) {
        float w;
        if (col >= NK) {
            w = 0.f;
        } else if (!isPose) {
            w = s;
        } else {
            w = s - s0;
            int a1 = c_NB1[j], a2 = c_NB2[j];
            if (row >= a1 && row < a1 + 3) w += g_M1[j * 9 + (row - a1) * 3 + o];
            if (row >= a2 && row < a2 + 3) w += g_M2[j * 9 + (row - a2) * 3 + o];
            // subtract joint-0 neighbor scatter (NB1[0]=51, NB2[0]=54)
            if (row >= 51 && row < 54) w -= g_M1[(row - 51) * 3 + o];
            if (row >= 54 && row < 57) w -= g_M2[(row - 54) * 3 + o];
        }
        g_W[row * NKPAD + col] = w;
    } else {
        float bv;
        if      (col >= NK) bv = 0.f;
        else if (col < 10)  bv = s + b_shape[col] + init_shape[col];
        else if (col < 13)  bv = s + b_cam[col - 10] + init_cam[col - 10];
        else if (col < 59)  bv = s + b_phi[col - 13];
        else if (col < 79)  bv = s + b_leaf[col - 59];
        else {
            float bt = s  + reg_b[t] + g_bp1[t] + g_bp2[t];
            float b0 = s0 + reg_b[o] + g_bp1[o] + g_bp2[o];
            bv = bt - b0;
        }
        g_b[col] = bv;
    }
}

// ---------------------------------------------------------------------------
// Kernel C: main — out(B,151) = x(B,57) @ W' + b'. Branchless GEMM.
// Block = 128 threads covering 64 rows x 16 cols (ty=row, tx=col half,
// 8 cols per thread). Low smem (18.5 KB) + low regs -> high occupancy.
// grid = (B/64, 10 slices).
// ---------------------------------------------------------------------------
__global__ void __launch_bounds__(128)
main_kernel(const float* __restrict__ joints, float* __restrict__ out, int B)
{
    __shared__ float  Xs[RPB * NC];       // 64*57*4 = 14592 B, stride 57 (odd)
    __shared__ float4 Ws4[NC][SLICE_W / 4];  // 16 cols of W' per block
    __shared__ float  bias_s[SLICE_W];

    const int tid = threadIdx.x;
    const int rb  = blockIdx.x * RPB;
    const int k0  = blockIdx.y * SLICE_W;    // 0,16,...,144
    const int nrows = min(RPB, B - rb);

    // output section offsets (pose first, per metadata layout)
    const int CAM_OFF   = B * 72;
    const int PHI_OFF   = CAM_OFF + B * 3;
    const int LEAF_OFF  = PHI_OFF + B * 46;
    const int SHAPE_OFF = LEAF_OFF + B * 20;

    // stage X: coalesced gmem read, sequential smem write
    for (int idx = tid; idx < nrows * NC; idx += 128)
        Xs[idx] = joints[rb * NC + idx];

    // load this block's 16 W' columns
    for (int idx = tid; idx < NC * SLICE_W; idx += 128) {
        int c = idx / SLICE_W, e = idx - c * SLICE_W;
        ((float*)Ws4)[c * SLICE_W + e] = g_W[c * NKPAD + k0 + e];
    }
    if (tid < SLICE_W) bias_s[tid] = g_b[k0 + tid];
    __syncthreads();

    const int ty = tid >> 1;          // row within tile (0..63)
    const int tx = tid & 1;           // column half (0/1)
    if (ty >= nrows) return;
    const int b  = rb + ty;
    const int kb = k0 + tx * 8;       // first of this thread's 8 columns

    float4 a0 = make_float4(bias_s[tx * 8 + 0], bias_s[tx * 8 + 1],
                            bias_s[tx * 8 + 2], bias_s[tx * 8 + 3]);
    float4 a1 = make_float4(bias_s[tx * 8 + 4], bias_s[tx * 8 + 5],
                            bias_s[tx * 8 + 6], bias_s[tx * 8 + 7]);

    const float* xrow = &Xs[ty * NC];
    #pragma unroll
    for (int c = 0; c < NC; c++) {
        float  xc = xrow[c];
        float4 w0 = Ws4[c][tx * 2];
        float4 w1 = Ws4[c][tx * 2 + 1];
        a0.x = fmaf(xc, w0.x, a0.x); a0.y = fmaf(xc, w0.y, a0.y);
        a0.z = fmaf(xc, w0.z, a0.z); a0.w = fmaf(xc, w0.w, a0.w);
        a1.x = fmaf(xc, w1.x, a1.x); a1.y = fmaf(xc, w1.y, a1.y);
        a1.z = fmaf(xc, w1.z, a1.z); a1.w = fmaf(xc, w1.w, a1.w);
    }

    float v[8] = {a0.x, a0.y, a0.z, a0.w, a1.x, a1.y, a1.z, a1.w};
    #pragma unroll
    for (int e = 0; e < 8; e++) {
        int k = kb + e;
        if (k < NK) {
            float val = v[e];
            if      (k < 10) out[SHAPE_OFF + b * 10 + k]        = val;
            else if (k < 13) out[CAM_OFF   + b * 3  + (k - 10)] = val;
            else if (k < 59) out[PHI_OFF   + b * 46 + (k - 13)] = val;
            else if (k < 79) out[LEAF_OFF  + b * 20 + (k - 59)] = val;
            else             out[b * 72 + (k - 79)]             = val;
        }
    }
}

// ---------------------------------------------------------------------------
extern "C" void kernel_launch(void* const* d_in, const int* in_sizes, int n_in,
                              void* d_out, int out_size)
{
    const float* joints     = (const float*)d_in[0];
    const float* W_enc      = (const float*)d_in[1];
    const float* b_enc      = (const float*)d_in[2];
    const float* W_shape    = (const float*)d_in[3];
    const float* b_shape    = (const float*)d_in[4];
    const float* W_cam      = (const float*)d_in[5];
    const float* b_cam      = (const float*)d_in[6];
    const float* W_phi      = (const float*)d_in[7];
    const float* b_phi      = (const float*)d_in[8];
    const float* W_leaf     = (const float*)d_in[9];
    const float* b_leaf     = (const float*)d_in[10];
    const float* init_shape = (const float*)d_in[11];
    const float* init_cam   = (const float*)d_in[12];
    const float* L1_w       = (const float*)d_in[13];
    const float* L1_b       = (const float*)d_in[14];
    const float* L2_w       = (const float*)d_in[15];
    const float* L2_b       = (const float*)d_in[16];
    const float* Rf         = (const float*)d_in[17];
    const float* R1         = (const float*)d_in[18];
    const float* R2         = (const float*)d_in[19];
    const float* reg_b      = (const float*)d_in[20];

    int B = in_sizes[0] / NC;

    precompute_kernel<<<5 * KSPLIT + 72, 256>>>(W_enc, b_enc, W_shape, W_cam, W_phi, W_leaf, Rf,
                                                L1_w, L1_b, L2_w, L2_b, R1, R2);
    finalize_kernel<<<58, NKPAD>>>(b_shape, b_cam, b_phi, b_leaf, init_shape, init_cam, reg_b);
    main_kernel<<<dim3((B + RPB - 1) / RPB, NSLICES), 128>>>(joints, (float*)d_out, B);
}

// round 4
// speedup vs baseline: 1.9941x; 1.0850x over previous
#include <cuda_runtime.h>

// ---------------------------------------------------------------------------
// Pose2Mesh fully-collapsed linear implementation.
// All heads + neighbor 3x3 contractions + root subtraction folded into one
// dense W'(57 x 151) + b'(151); main kernel = out(B,151) = x(B,57) @ W' + b'
// using packed fma.rn.f32x2 (FFMA2).
// ---------------------------------------------------------------------------

#define D_DIM   2048
#define NC      57      // J*3
#define NK      151
#define NKPAD   160
#define KSPLIT  64
#define H_DIM   512
#define CPB     32      // cols per block (main)
#define NSLICES 5       // 160/32
#define RPB     64      // rows per block (main)

// scratch (allocation-free: __device__ globals)
__device__ float g_M1[24 * 9];
__device__ float g_M2[24 * 9];
__device__ float g_bp1[72];
__device__ float g_bp2[72];
__device__ float g_Wpart[KSPLIT * 58 * NKPAD];
__device__ float g_W[NC * NKPAD];
__device__ float g_b[NKPAD];

// NEB1[j]*3 and NEB2[j]*3 (base offsets into the 57-float joint vector)
__constant__ int c_NB1[24] = {51,33,36,51,39,42,51,45,48,54,45,48,54,54,54,54,15,18,21,24,27,30,27,30};
__constant__ int c_NB2[24] = {54,51,51,54,33,36,54,39,42,51,39,42, 0,15,18, 0,54,54,15,18,21,24,21,24};

// ---------------------------------------------------------------------------
// Kernel A (fused): blocks [0, 5*KSPLIT) = fold GEMM split-K partials,
//                   blocks [5*KSPLIT, +72) = per-joint 3x3 M1/M2 + bias dots
// ---------------------------------------------------------------------------
__device__ __forceinline__ float fetchB(int f, int col,
                                        const float* __restrict__ Wsh, const float* __restrict__ Wca,
                                        const float* __restrict__ Wph, const float* __restrict__ Wlf,
                                        const float* __restrict__ Rf)
{
    if (col < 10)  return Wsh[f * 10 + col];
    if (col < 13)  return Wca[f * 3  + (col - 10)];
    if (col < 59)  return Wph[f * 46 + (col - 13)];
    if (col < 79)  return Wlf[f * 20 + (col - 59)];
    int t = col - 79;
    int j = t / 3, o = t - j * 3;
    return Rf[(j * D_DIM + f) * 3 + o];
}

__global__ void __launch_bounds__(256)
precompute_kernel(const float* __restrict__ W_enc, const float* __restrict__ b_enc,
                  const float* __restrict__ W_shape, const float* __restrict__ W_cam,
                  const float* __restrict__ W_phi,   const float* __restrict__ W_leaf,
                  const float* __restrict__ Rf,
                  const float* __restrict__ L1_w, const float* __restrict__ L1_b,
                  const float* __restrict__ L2_w, const float* __restrict__ L2_b,
                  const float* __restrict__ R1,   const float* __restrict__ R2)
{
    int bx  = blockIdx.x;
    int tid = threadIdx.x;

    if (bx >= 5 * KSPLIT) {
        // ---- compute_M: 72 blocks x 8 warps; one warp per (j, t) dot of len 512
        int mb   = bx - 5 * KSPLIT;       // 0..71
        int j    = mb % 24;
        int g    = mb / 24;               // 0..2
        int lane = tid & 31;
        int t    = g * 8 + (tid >> 5);    // 0..23

        const float* ap;
        const float* rp;
        if (t < 9) {
            int c = t / 3, o = t % 3;
            ap = L1_w + (j * 3 + c) * H_DIM;
            rp = R1 + j * H_DIM * 3 + o;
        } else if (t < 18) {
            int tt = t - 9; int c = tt / 3, o = tt % 3;
            ap = L2_w + (j * 3 + c) * H_DIM;
            rp = R2 + j * H_DIM * 3 + o;
        } else if (t < 21) {
            int o = t - 18;
            ap = L1_b + j * H_DIM;
            rp = R1 + j * H_DIM * 3 + o;
        } else {
            int o = t - 21;
            ap = L2_b + j * H_DIM;
            rp = R2 + j * H_DIM * 3 + o;
        }
        // batched loads: full unroll (constant trip), all 32 LDGs in flight
        float av[16], rv[16];
        #pragma unroll
        for (int i = 0; i < 16; i++) {
            int h = lane + 32 * i;
            av[i] = ap[h];
            rv[i] = rp[h * 3];
        }
        float sum = 0.f;
        #pragma unroll
        for (int i = 0; i < 16; i++) sum = fmaf(av[i], rv[i], sum);
        #pragma unroll
        for (int d = 16; d > 0; d >>= 1) sum += __shfl_xor_sync(0xffffffffu, sum, d);
        if (lane == 0) {
            if      (t < 9)  g_M1[j * 9 + t]          = sum;
            else if (t < 18) g_M2[j * 9 + (t - 9)]    = sum;
            else if (t < 21) g_bp1[j * 3 + (t - 18)]  = sum;
            else             g_bp2[j * 3 + (t - 21)]  = sum;
        }
        return;
    }

    // ---- fold GEMM: single K=32 phase per block, split-K partials
    __shared__ float As[64][33];
    __shared__ __align__(16) float Bs[32][36];

    int ct = bx % 5;              // column tile (5 tiles of 32 -> 160)
    int ks = bx / 5;              // k-split index (0..63)
    int kbase = ks * 32;

    // batched A loads (2048 elems / 256 thr = 8 each)
    float va[8];
    #pragma unroll
    for (int i = 0; i < 8; i++) {
        int idx = tid + 256 * i;
        int r = idx >> 5, kk = idx & 31;
        float v = 0.f;
        if (r < NC)       v = W_enc[r * D_DIM + kbase + kk];
        else if (r == NC) v = b_enc[kbase + kk];
        va[i] = v;
    }
    // batched B loads (1024 / 256 = 4 each)
    float vb[4];
    #pragma unroll
    for (int i = 0; i < 4; i++) {
        int idx = tid + 256 * i;
        int kk = idx >> 5, cl = idx & 31;
        int gcol = ct * 32 + cl;
        vb[i] = (gcol < NK) ? fetchB(kbase + kk, gcol, W_shape, W_cam, W_phi, W_leaf, Rf) : 0.f;
    }
    #pragma unroll
    for (int i = 0; i < 8; i++) {
        int idx = tid + 256 * i;
        As[idx >> 5][idx & 31] = va[i];
    }
    #pragma unroll
    for (int i = 0; i < 4; i++) {
        int idx = tid + 256 * i;
        Bs[idx >> 5][idx & 31] = vb[i];
    }
    __syncthreads();

    // compute: thread = (row r, col group cg of 8)
    int r  = tid >> 2;            // 0..63
    int cg = tid & 3;             // 0..3
    float acc[8];
    #pragma unroll
    for (int e = 0; e < 8; e++) acc[e] = 0.f;
    #pragma unroll
    for (int kk = 0; kk < 32; kk++) {
        float  xc = As[r][kk];
        float4 w0 = *(const float4*)&Bs[kk][cg * 8];
        float4 w1 = *(const float4*)&Bs[kk][cg * 8 + 4];
        acc[0] = fmaf(xc, w0.x, acc[0]); acc[1] = fmaf(xc, w0.y, acc[1]);
        acc[2] = fmaf(xc, w0.z, acc[2]); acc[3] = fmaf(xc, w0.w, acc[3]);
        acc[4] = fmaf(xc, w1.x, acc[4]); acc[5] = fmaf(xc, w1.y, acc[5]);
        acc[6] = fmaf(xc, w1.z, acc[6]); acc[7] = fmaf(xc, w1.w, acc[7]);
    }
    if (r < 58) {
        float* dst = &g_Wpart[(ks * 58 + r) * NKPAD + ct * 32 + cg * 8];
        *(float4*)dst       = make_float4(acc[0], acc[1], acc[2], acc[3]);
        *(float4*)(dst + 4) = make_float4(acc[4], acc[5], acc[6], acc[7]);
    }
}

// ---------------------------------------------------------------------------
// Kernel B: reduce split-K partials, fold neighbor 3x3 terms AND the root
// (joint 0) subtraction directly into W' and b'. Pads cols [151,160) to 0.
// ---------------------------------------------------------------------------
__global__ void finalize_kernel(const float* __restrict__ b_shape, const float* __restrict__ b_cam,
                                const float* __restrict__ b_phi,   const float* __restrict__ b_leaf,
                                const float* __restrict__ init_shape, const float* __restrict__ init_cam,
                                const float* __restrict__ reg_b)
{
    int row = blockIdx.x;    // 0..57
    int col = threadIdx.x;   // 0..159
    float s = 0.f;
    #pragma unroll
    for (int p = 0; p < KSPLIT; p++) s += g_Wpart[(p * 58 + row) * NKPAD + col];

    bool isPose = (col >= 79 && col < NK);
    int t = 0, j = 0, o = 0;
    float s0 = 0.f;
    if (isPose) {
        t = col - 79; j = t / 3; o = t - 3 * j;
        #pragma unroll
        for (int p = 0; p < KSPLIT; p++) s0 += g_Wpart[(p * 58 + row) * NKPAD + 79 + o];
    }

    if (row < NC) {
        float w;
        if (col >= NK) {
            w = 0.f;
        } else if (!isPose) {
            w = s;
        } else {
            w = s - s0;
            int a1 = c_NB1[j], a2 = c_NB2[j];
            if (row >= a1 && row < a1 + 3) w += g_M1[j * 9 + (row - a1) * 3 + o];
            if (row >= a2 && row < a2 + 3) w += g_M2[j * 9 + (row - a2) * 3 + o];
            // subtract joint-0 neighbor scatter (NB1[0]=51, NB2[0]=54)
            if (row >= 51 && row < 54) w -= g_M1[(row - 51) * 3 + o];
            if (row >= 54 && row < 57) w -= g_M2[(row - 54) * 3 + o];
        }
        g_W[row * NKPAD + col] = w;
    } else {
        float bv;
        if      (col >= NK) bv = 0.f;
        else if (col < 10)  bv = s + b_shape[col] + init_shape[col];
        else if (col < 13)  bv = s + b_cam[col - 10] + init_cam[col - 10];
        else if (col < 59)  bv = s + b_phi[col - 13];
        else if (col < 79)  bv = s + b_leaf[col - 59];
        else {
            float bt = s  + reg_b[t] + g_bp1[t] + g_bp2[t];
            float b0 = s0 + reg_b[o] + g_bp1[o] + g_bp2[o];
            bv = bt - b0;
        }
        g_b[col] = bv;
    }
}

// ---------------------------------------------------------------------------
// Kernel C: main — out(B,151) = x(B,57) @ W' + b'. FFMA2 (fma.rn.f32x2).
// Block = 128 threads covering 64 rows x 32 cols: thread = 2 rows x 8 cols.
// grid = (B/64, 5 slices).
// ---------------------------------------------------------------------------
__global__ void __launch_bounds__(128)
main_kernel(const float* __restrict__ joints, float* __restrict__ out, int B)
{
    __shared__ __align__(16) float Xs[RPB * NC];     // 64*57*4 = 14592 B
    __shared__ __align__(16) float Ws[NC][CPB];      // 57*32*4 = 7296 B
    __shared__ float bias_s[CPB];

    const int tid = threadIdx.x;
    const int rb  = blockIdx.x * RPB;
    const int k0  = blockIdx.y * CPB;

    // output section offsets (pose first, per output layout)
    const int CAM_OFF   = B * 72;
    const int PHI_OFF   = CAM_OFF + B * 3;
    const int LEAF_OFF  = PHI_OFF + B * 46;
    const int SHAPE_OFF = LEAF_OFF + B * 20;

    // ---- stage X (batched) ----
    if (rb + RPB <= B) {
        // fast path: 64*57 floats = 912 float4, 16B-aligned (rb%64==0)
        const float4* jp = (const float4*)(joints + rb * NC);
        float4 xv[8];
        #pragma unroll
        for (int i = 0; i < 8; i++) {
            int idx = tid + 128 * i;
            if (idx < 912) xv[i] = jp[idx];
        }
        #pragma unroll
        for (int i = 0; i < 8; i++) {
            int idx = tid + 128 * i;
            if (idx < 912) ((float4*)Xs)[idx] = xv[i];
        }
    } else {
        int nr = B - rb;
        for (int idx = tid; idx < nr * NC; idx += 128)
            Xs[idx] = joints[rb * NC + idx];
    }

    // ---- stage W slice (batched): 57 rows x 8 float4 = 456 float4 ----
    {
        float4 wv[4];
        #pragma unroll
        for (int i = 0; i < 4; i++) {
            int idx = tid + 128 * i;
            if (idx < 456) {
                int r = idx >> 3, q = idx & 7;
                wv[i] = *(const float4*)(g_W + r * NKPAD + k0 + q * 4);
            }
        }
        #pragma unroll
        for (int i = 0; i < 4; i++) {
            int idx = tid + 128 * i;
            if (idx < 456) {
                int r = idx >> 3, q = idx & 7;
                *(float4*)&Ws[r][q * 4] = wv[i];
            }
        }
    }
    if (tid < CPB) bias_s[tid] = g_b[k0 + tid];
    __syncthreads();

    const int ty = tid >> 2;          // 0..31 -> rows 2ty, 2ty+1
    const int cg = tid & 3;           // col group: cols cg*8 .. cg*8+7
    const int r0 = 2 * ty, r1 = r0 + 1;

    // accumulators: 2 rows x 4 f32x2 (8 outputs per row)
    unsigned long long accA[4], accB[4];
    #pragma unroll
    for (int e = 0; e < 4; e++) {
        float lo = bias_s[cg * 8 + 2 * e];
        float hi = bias_s[cg * 8 + 2 * e + 1];
        unsigned long long p;
        asm("mov.b64 %0, {%1, %2};" : "=l"(p) : "f"(lo), "f"(hi));
        accA[e] = p; accB[e] = p;
    }

    const float* x0 = &Xs[r0 * NC];
    const float* x1 = &Xs[r1 * NC];
    #pragma unroll
    for (int c = 0; c < NC; c++) {
        float a = x0[c], b = x1[c];
        unsigned long long xa, xb;
        asm("mov.b64 %0, {%1, %1};" : "=l"(xa) : "f"(a));
        asm("mov.b64 %0, {%1, %1};" : "=l"(xb) : "f"(b));
        const ulonglong2* wp = (const ulonglong2*)&Ws[c][cg * 8];
        ulonglong2 wv0 = wp[0];   // cols 0..3 as two f32x2
        ulonglong2 wv1 = wp[1];   // cols 4..7
        asm("fma.rn.f32x2 %0, %1, %2, %0;" : "+l"(accA[0]) : "l"(xa), "l"(wv0.x));
        asm("fma.rn.f32x2 %0, %1, %2, %0;" : "+l"(accA[1]) : "l"(xa), "l"(wv0.y));
        asm("fma.rn.f32x2 %0, %1, %2, %0;" : "+l"(accA[2]) : "l"(xa), "l"(wv1.x));
        asm("fma.rn.f32x2 %0, %1, %2, %0;" : "+l"(accA[3]) : "l"(xa), "l"(wv1.y));
        asm("fma.rn.f32x2 %0, %1, %2, %0;" : "+l"(accB[0]) : "l"(xb), "l"(wv0.x));
        asm("fma.rn.f32x2 %0, %1, %2, %0;" : "+l"(accB[1]) : "l"(xb), "l"(wv0.y));
        asm("fma.rn.f32x2 %0, %1, %2, %0;" : "+l"(accB[2]) : "l"(xb), "l"(wv1.x));
        asm("fma.rn.f32x2 %0, %1, %2, %0;" : "+l"(accB[3]) : "l"(xb), "l"(wv1.y));
    }

    // unpack + store (section-mapped), both rows
    #pragma unroll
    for (int rr = 0; rr < 2; rr++) {
        int b = rb + (rr == 0 ? r0 : r1);
        if (b >= B) continue;
        const unsigned long long* acc = (rr == 0) ? accA : accB;
        float v[8];
        #pragma unroll
        for (int e = 0; e < 4; e++) {
            float lo, hi;
            asm("mov.b64 {%0, %1}, %2;" : "=f"(lo), "=f"(hi) : "l"(acc[e]));
            v[2 * e] = lo; v[2 * e + 1] = hi;
        }
        #pragma unroll
        for (int e = 0; e < 8; e++) {
            int k = k0 + cg * 8 + e;
            if (k < NK) {
                float val = v[e];
                if      (k < 10) out[SHAPE_OFF + b * 10 + k]        = val;
                else if (k < 13) out[CAM_OFF   + b * 3  + (k - 10)] = val;
                else if (k < 59) out[PHI_OFF   + b * 46 + (k - 13)] = val;
                else if (k < 79) out[LEAF_OFF  + b * 20 + (k - 59)] = val;
                else             out[b * 72 + (k - 79)]             = val;
            }
        }
    }
}

// ---------------------------------------------------------------------------
extern "C" void kernel_launch(void* const* d_in, const int* in_sizes, int n_in,
                              void* d_out, int out_size)
{
    const float* joints     = (const float*)d_in[0];
    const float* W_enc      = (const float*)d_in[1];
    const float* b_enc      = (const float*)d_in[2];
    const float* W_shape    = (const float*)d_in[3];
    const float* b_shape    = (const float*)d_in[4];
    const float* W_cam      = (const float*)d_in[5];
    const float* b_cam      = (const float*)d_in[6];
    const float* W_phi      = (const float*)d_in[7];
    const float* b_phi      = (const float*)d_in[8];
    const float* W_leaf     = (const float*)d_in[9];
    const float* b_leaf     = (const float*)d_in[10];
    const float* init_shape = (const float*)d_in[11];
    const float* init_cam   = (const float*)d_in[12];
    const float* L1_w       = (const float*)d_in[13];
    const float* L1_b       = (const float*)d_in[14];
    const float* L2_w       = (const float*)d_in[15];
    const float* L2_b       = (const float*)d_in[16];
    const float* Rf         = (const float*)d_in[17];
    const float* R1         = (const float*)d_in[18];
    const float* R2         = (const float*)d_in[19];
    const float* reg_b      = (const float*)d_in[20];

    int B = in_sizes[0] / NC;

    precompute_kernel<<<5 * KSPLIT + 72, 256>>>(W_enc, b_enc, W_shape, W_cam, W_phi, W_leaf, Rf,
                                                L1_w, L1_b, L2_w, L2_b, R1, R2);
    finalize_kernel<<<58, NKPAD>>>(b_shape, b_cam, b_phi, b_leaf, init_shape, init_cam, reg_b);
    main_kernel<<<dim3((B + RPB - 1) / RPB, NSLICES), 128>>>(joints, (float*)d_out, B);
}